// round 17
// baseline (speedup 1.0000x reference)
#include <cuda_runtime.h>
#include <cuda_fp16.h>
#include <math.h>
#include <stdint.h>

// ---------------- problem constants ----------------
#define M_ROWS 4096      // B*S
#define HDIM   896
#define DHEAD  128
#define NHEADS 7
#define SEQ    2048
#define QKV_N  1152      // 7*128 + 128 + 128
#define IDIM   4864

#define GSTRIDE 36       // gemm smem stride (32-bit words); 36 mod 32 == 4
#define FKS 68           // flash Q/K/V smem stride (words); 68 mod 32 == 4
#define FPW 36           // flash P smem stride (words)

// ---------------- scratch (device globals; no runtime alloc) ----------------
__device__ float  g_x2  [M_ROWS * HDIM];
__device__ __half g_h1h [M_ROWS * HDIM];
__device__ __half g_h2h [M_ROWS * HDIM];
__device__ __half g_attnh[M_ROWS * HDIM];
__device__ __half g_qkvh[M_ROWS * QKV_N];
__device__ __half g_gah [(size_t)M_ROWS * IDIM];
__device__ __half g_wqkvh[QKV_N * HDIM];
__device__ float  g_bqkv[QKV_N];
// half weight copies: wo | wgu (interleaved gate/up) | wd
#define WO_OFF 0
#define WGU_OFF (HDIM * HDIM)
#define WD_OFF (WGU_OFF + 2 * IDIM * HDIM)
#define WRND_TOTAL (WD_OFF + IDIM * HDIM)
__device__ __half g_wh[WRND_TOTAL];

// ---------------- helpers ----------------
__device__ __forceinline__ uint32_t pack2h(float a, float b) {
    __half2 h = __floats2half2_rn(a, b);
    return *(uint32_t*)&h;
}
__device__ __forceinline__ void mma_f16(float* c, const uint32_t* a, const uint32_t* b) {
    asm volatile(
        "mma.sync.aligned.m16n8k16.row.col.f32.f16.f16.f32 "
        "{%0,%1,%2,%3}, {%4,%5,%6,%7}, {%8,%9}, {%0,%1,%2,%3};"
        : "+f"(c[0]), "+f"(c[1]), "+f"(c[2]), "+f"(c[3])
        : "r"(a[0]), "r"(a[1]), "r"(a[2]), "r"(a[3]), "r"(b[0]), "r"(b[1]));
}
__device__ __forceinline__ uint32_t smem_u32(const void* p) {
    uint32_t a;
    asm("{ .reg .u64 t; cvta.to.shared.u64 t, %1; cvt.u32.u64 %0, t; }" : "=r"(a) : "l"(p));
    return a;
}
__device__ __forceinline__ void cp16(uint32_t dst, const void* src) {
    asm volatile("cp.async.cg.shared.global [%0], [%1], 16;" :: "r"(dst), "l"(src));
}
#define LDM_X4(r0, r1, r2, r3, addr) \
    asm volatile("ldmatrix.sync.aligned.m8n8.x4.shared.b16 {%0,%1,%2,%3}, [%4];" \
        : "=r"(r0), "=r"(r1), "=r"(r2), "=r"(r3) : "r"(addr))
#define LDM_X4T(r0, r1, r2, r3, addr) \
    asm volatile("ldmatrix.sync.aligned.m8n8.x4.trans.shared.b16 {%0,%1,%2,%3}, [%4];" \
        : "=r"(r0), "=r"(r1), "=r"(r2), "=r"(r3) : "r"(addr))

// ---------------- fp32 -> fp16 weight conversion ----------------
__global__ void __launch_bounds__(256) cvt_h_kernel(const float* __restrict__ in,
                                                    __half* __restrict__ out, int n4)
{
    const int i = blockIdx.x * 256 + threadIdx.x;
    if (i < n4) {
        float4 v = ((const float4*)in)[i];
        uint2 o;
        o.x = pack2h(v.x, v.y);
        o.y = pack2h(v.z, v.w);
        ((uint2*)out)[i] = o;
    }
}
// interleaved: in row r -> out row 2r+off (for merged gate/up weight)
__global__ void __launch_bounds__(256) cvt_h_int_kernel(const float* __restrict__ in,
                                                        __half* __restrict__ out, int off)
{
    const int i = blockIdx.x * 256 + threadIdx.x;   // 4-float chunk id
    const int n4 = IDIM * HDIM / 4;
    if (i < n4) {
        const int row = (i * 4) / HDIM;
        const int col = (i * 4) % HDIM;
        float4 v = ((const float4*)in)[i];
        uint2 o;
        o.x = pack2h(v.x, v.y);
        o.y = pack2h(v.z, v.w);
        *(uint2*)(out + (size_t)(2 * row + off) * HDIM + col) = o;
    }
}

// ---------------- RMSNorm (fp16 output: pure GEMM A operand) ----------------
__global__ void __launch_bounds__(256) rmsnorm_kernel(const float* __restrict__ x,
                                                      const float* __restrict__ w,
                                                      __half* __restrict__ out)
{
    __shared__ float red[256];
    const int row = blockIdx.x;
    const float* xr = x + (size_t)row * HDIM;
    float ss = 0.f;
    for (int i = threadIdx.x; i < HDIM; i += 256) { float v = xr[i]; ss += v * v; }
    red[threadIdx.x] = ss;
    __syncthreads();
    for (int s = 128; s > 0; s >>= 1) {
        if (threadIdx.x < s) red[threadIdx.x] += red[threadIdx.x + s];
        __syncthreads();
    }
    const float inv = rsqrtf(red[0] / (float)HDIM + 1e-6f);
    __half* orow = out + (size_t)row * HDIM;
    for (int i = threadIdx.x; i < HDIM; i += 256)
        orow[i] = __float2half_rn(xr[i] * inv * w[i]);
}

// ---------------- fp16 mma GEMM, 256x128 CTA tile, cp.async 3-stage ---------
// 8 warps in 4x2, each warp 64x64 (mma:ldmatrix = 4.0). k-chunk = 64 halves.
// MODE 0: +bias[n] -> half. MODE 1: +aux[m,n](fp32) -> fp32.
// MODE 2: col pairs (gate,up): silu(v0)*v1 -> half at n/2 (out width N/2).
template<int MODE>
__global__ void __launch_bounds__(256) gemm_h(const __half* __restrict__ A,
                                              const __half* __restrict__ B,
                                              const float* __restrict__ bias,
                                              const void* __restrict__ aux,
                                              void* __restrict__ Cv,
                                              int M, int N, int K)
{
    extern __shared__ float sm[];
    const uint32_t sbase = smem_u32(sm);
    constexpr uint32_t STG = (256 + 128) * GSTRIDE;   // words per stage (A+B)

    const int tid = threadIdx.x;
    const int wid = tid >> 5, lane = tid & 31;
    const int lq = lane >> 2, lr = lane & 3;
    const int warp_m = wid >> 1, warp_n = wid & 1;    // 4 x 2
    const int rowbase = warp_m * 64, colbase = warp_n * 64;
    const int m0 = blockIdx.y * 256, n0 = blockIdx.x * 128;

    const int pr = tid >> 3;          // 0..31 (row step 32)
    const int pc = (tid & 7) << 2;    // word col 0..28 (16B per thread)

    const int l7 = lane & 7;
    const int aRow = rowbase + l7 + ((lane & 8) ? 8 : 0);
    const int aKw  = (lane & 16) ? 4 : 0;
    const int bRow = colbase + l7 + ((lane & 16) ? 8 : 0);
    const int bKw  = (lane & 8) ? 4 : 0;

    float acc[4][8][4];
#pragma unroll
    for (int i = 0; i < 4; i++)
#pragma unroll
        for (int j = 0; j < 8; j++)
#pragma unroll
            for (int q = 0; q < 4; q++) acc[i][j][q] = 0.f;

    const int nch = K >> 6;           // 64 halves per chunk
    const __half* Abase = A + (size_t)m0 * K;
    const __half* Bbase = B + (size_t)n0 * K;

#define ISSUE(CH, S) do { \
        const __half* Ap_ = Abase + (CH) * 64; \
        const __half* Bp_ = Bbase + (CH) * 64; \
        const uint32_t sA_ = sbase + (S) * STG * 4; \
        const uint32_t sB_ = sA_ + 256 * GSTRIDE * 4; \
        _Pragma("unroll") \
        for (int p_ = 0; p_ < 8; ++p_) { \
            const int r_ = pr + p_ * 32; \
            cp16(sA_ + (uint32_t)(r_ * GSTRIDE + pc) * 4, Ap_ + (size_t)r_ * K + pc * 2); \
        } \
        _Pragma("unroll") \
        for (int p_ = 0; p_ < 4; ++p_) { \
            const int r_ = pr + p_ * 32; \
            cp16(sB_ + (uint32_t)(r_ * GSTRIDE + pc) * 4, Bp_ + (size_t)r_ * K + pc * 2); \
        } \
    } while (0)

    ISSUE(0, 0);
    asm volatile("cp.async.commit_group;");
    if (nch > 1) ISSUE(1, 1);
    asm volatile("cp.async.commit_group;");

    for (int ch = 0; ch < nch; ++ch) {
        if (ch + 1 < nch) asm volatile("cp.async.wait_group 1;");
        else              asm volatile("cp.async.wait_group 0;");
        __syncthreads();
        if (ch + 2 < nch) {           // safe: overwritten stage's readers ran pre-barrier
            ISSUE(ch + 2, (ch + 2) % 3);
            asm volatile("cp.async.commit_group;");
        }

        const uint32_t sA = sbase + (uint32_t)(ch % 3) * STG * 4;
        const uint32_t sB = sA + 256 * GSTRIDE * 4;
#pragma unroll
        for (int ks = 0; ks < 4; ++ks) {    // 4 x k16
            uint32_t af[4][4], bf[8][2];
#pragma unroll
            for (int i = 0; i < 4; ++i)
                LDM_X4(af[i][0], af[i][1], af[i][2], af[i][3],
                       sA + (uint32_t)((aRow + i * 16) * GSTRIDE + ks * 8 + aKw) * 4);
#pragma unroll
            for (int jp = 0; jp < 4; ++jp)
                LDM_X4(bf[2 * jp][0], bf[2 * jp][1], bf[2 * jp + 1][0], bf[2 * jp + 1][1],
                       sB + (uint32_t)((bRow + jp * 16) * GSTRIDE + ks * 8 + bKw) * 4);
#pragma unroll
            for (int i = 0; i < 4; ++i)
#pragma unroll
                for (int j = 0; j < 8; ++j)
                    mma_f16(acc[i][j], af[i], bf[j]);
        }
    }
#undef ISSUE

    // epilogue
#pragma unroll
    for (int i = 0; i < 4; ++i) {
#pragma unroll
        for (int half_ = 0; half_ < 2; ++half_) {
            const int m = m0 + rowbase + i * 16 + lq + half_ * 8;
#pragma unroll
            for (int j = 0; j < 8; ++j) {
                const int n = n0 + colbase + j * 8 + 2 * lr;
                float v0 = acc[i][j][half_ * 2 + 0];
                float v1 = acc[i][j][half_ * 2 + 1];
                if (MODE == 0) {
                    v0 += bias[n]; v1 += bias[n + 1];
                    *(uint32_t*)((__half*)Cv + (size_t)m * N + n) = pack2h(v0, v1);
                } else if (MODE == 1) {
                    const float* arow = (const float*)aux + (size_t)m * N;
                    v0 += arow[n]; v1 += arow[n + 1];
                    *(float2*)((float*)Cv + (size_t)m * N + n) = make_float2(v0, v1);
                } else {
                    // (gate, up) pair -> silu(gate)*up at col n/2
                    const float r = v0 / (1.f + __expf(-v0)) * v1;
                    ((__half*)Cv)[(size_t)m * (N >> 1) + (n >> 1)] = __float2half_rn(r);
                }
            }
        }
    }
}

// ---------------- RoPE (fp16 in-place; q heads pre-scaled by 1/sqrt(d)) -----
__global__ void rope_h_kernel(__half* __restrict__ qkv,
                              const float* __restrict__ cosT,
                              const float* __restrict__ sinT)
{
    const int row  = blockIdx.x;
    const int unit = blockIdx.y;     // 0..6 q heads, 7 = k
    const int d    = threadIdx.x;    // 0..63
    const int s    = row & (SEQ - 1);
    const float c  = cosT[s * DHEAD + d];
    const float sn = sinT[s * DHEAD + d];
    __half* p = qkv + (size_t)row * QKV_N + (unit < NHEADS ? unit * DHEAD : HDIM);
    const float x1 = __half2float(p[d]), x2 = __half2float(p[d + 64]);
    float r1 = x1 * c - x2 * sn;
    float r2 = x1 * sn + x2 * c;
    if (unit < NHEADS) {
        r1 *= 0.08838834764831845f;
        r2 *= 0.08838834764831845f;
    }
    p[d]      = __float2half_rn(r1);
    p[d + 64] = __float2half_rn(r2);
}

// ---------------- tensor-core causal flash attention (all-fp16 mma) ---------
// fp16 qkv input (Q pre-scaled). BQ=128, BK=64, 8 warps x 16 q-rows.
// K/V tiles double-buffered via cp.async.
__global__ void __launch_bounds__(256) flash_mma_kernel(const __half* __restrict__ qkv,
                                                        __half* __restrict__ out)
{
    extern __shared__ float sm[];
    const uint32_t sbQ = smem_u32(sm);                        // 128 x FKS words
    const uint32_t sbK0 = sbQ + 128 * FKS * 4;                // 64 x FKS per buf
    const uint32_t sbV0 = sbK0 + 2 * 64 * FKS * 4;
    const uint32_t sbP = sbV0 + 2 * 64 * FKS * 4;             // 128 x FPW
    uint32_t* Pw = (uint32_t*)sm + (sbP - sbQ) / 4;

    const int tid = threadIdx.x;
    const int wid = tid >> 5, lane = tid & 31;
    const int lq = lane >> 2, lr = lane & 3;
    const int b = blockIdx.z, h = blockIdx.y;
    const int q0 = ((int)gridDim.x - 1 - (int)blockIdx.x) * 128;   // heavy tiles first

    const int l7 = lane & 7;
    const int aRowOff = l7 + ((lane & 8) ? 8 : 0);
    const int aKw     = (lane & 16) ? 4 : 0;
    const int bRowOff = l7 + ((lane & 16) ? 8 : 0);
    const int bKw     = (lane & 8) ? 4 : 0;
    const int vK      = l7 + ((lane & 8) ? 8 : 0);
    const int vCol    = (lane & 16) ? 4 : 0;

    // producer indexing: 16B chunks; 16 chunks per 128-half row
    const int crow = tid >> 4;           // 0..15
    const int cw   = (tid & 15) << 2;    // word offset 0..60

#define ISSUE_Q() do { \
        _Pragma("unroll") \
        for (int p_ = 0; p_ < 8; ++p_) { \
            const int r_ = crow + p_ * 16; \
            cp16(sbQ + (uint32_t)(r_ * FKS + cw) * 4, \
                 qkv + ((size_t)(b * SEQ + q0 + r_)) * QKV_N + h * DHEAD + cw * 2); \
        } \
    } while (0)
#define ISSUE_KV(JT, S) do { \
        const uint32_t sK_ = sbK0 + (S) * 64 * FKS * 4; \
        const uint32_t sV_ = sbV0 + (S) * 64 * FKS * 4; \
        _Pragma("unroll") \
        for (int p_ = 0; p_ < 4; ++p_) { \
            const int r_ = crow + p_ * 16; \
            const __half* base_ = qkv + ((size_t)(b * SEQ + (JT) * 64 + r_)) * QKV_N; \
            cp16(sK_ + (uint32_t)(r_ * FKS + cw) * 4, base_ + HDIM + cw * 2); \
            cp16(sV_ + (uint32_t)(r_ * FKS + cw) * 4, base_ + HDIM + DHEAD + cw * 2); \
        } \
    } while (0)

    float oacc[16][4];
#pragma unroll
    for (int nf = 0; nf < 16; ++nf)
#pragma unroll
        for (int q = 0; q < 4; ++q) oacc[nf][q] = 0.f;
    float m0v = -1e30f, m1v = -1e30f, l0v = 0.f, l1v = 0.f;

    ISSUE_Q();
    ISSUE_KV(0, 0);
    asm volatile("cp.async.commit_group;");

    const int ntiles = q0 / 64 + 2;
    for (int jt = 0; jt < ntiles; ++jt) {
        const int buf = jt & 1;
        asm volatile("cp.async.wait_group 0;");
        __syncthreads();
        if (jt + 1 < ntiles) {        // safe post-barrier: buf^1 readers finished
            ISSUE_KV(jt + 1, buf ^ 1);
            asm volatile("cp.async.commit_group;");
        }
        const uint32_t sbK = sbK0 + (uint32_t)buf * 64 * FKS * 4;
        const uint32_t sbV = sbV0 + (uint32_t)buf * 64 * FKS * 4;

        // ---- S = Q @ K^T : fp16, 8 k16 steps over d=128 ----
        float sacc[8][4];
#pragma unroll
        for (int f = 0; f < 8; ++f)
#pragma unroll
            for (int q = 0; q < 4; ++q) sacc[f][q] = 0.f;

#pragma unroll
        for (int ks = 0; ks < 8; ++ks) {
            uint32_t af[4];
            LDM_X4(af[0], af[1], af[2], af[3],
                   sbQ + (uint32_t)((wid * 16 + aRowOff) * FKS + ks * 8 + aKw) * 4);
#pragma unroll
            for (int fp = 0; fp < 4; ++fp) {
                uint32_t b0a, b1a, b0b, b1b;
                LDM_X4(b0a, b1a, b0b, b1b,
                       sbK + (uint32_t)((fp * 16 + bRowOff) * FKS + ks * 8 + bKw) * 4);
                uint32_t bfa[2] = { b0a, b1a }, bfb[2] = { b0b, b1b };
                mma_f16(sacc[2 * fp],     af, bfa);
                mma_f16(sacc[2 * fp + 1], af, bfb);
            }
        }

        // causal mask
        if (jt * 64 + 63 > q0) {
            const int r0 = q0 + wid * 16 + lq;
#pragma unroll
            for (int f = 0; f < 8; ++f) {
                const int c0 = jt * 64 + f * 8 + 2 * lr;
                if (c0 > r0)     sacc[f][0] = -1e30f;
                if (c0 + 1 > r0) sacc[f][1] = -1e30f;
                if (c0 > r0 + 8)     sacc[f][2] = -1e30f;
                if (c0 + 1 > r0 + 8) sacc[f][3] = -1e30f;
            }
        }

        // ---- online softmax ----
        float mx0 = -1e30f, mx1 = -1e30f;
#pragma unroll
        for (int f = 0; f < 8; ++f) {
            mx0 = fmaxf(mx0, fmaxf(sacc[f][0], sacc[f][1]));
            mx1 = fmaxf(mx1, fmaxf(sacc[f][2], sacc[f][3]));
        }
        mx0 = fmaxf(mx0, __shfl_xor_sync(0xffffffffu, mx0, 1));
        mx0 = fmaxf(mx0, __shfl_xor_sync(0xffffffffu, mx0, 2));
        mx1 = fmaxf(mx1, __shfl_xor_sync(0xffffffffu, mx1, 1));
        mx1 = fmaxf(mx1, __shfl_xor_sync(0xffffffffu, mx1, 2));

        const float mn0 = fmaxf(m0v, mx0), mn1 = fmaxf(m1v, mx1);
        const float a0 = __expf(m0v - mn0), a1 = __expf(m1v - mn1);
        m0v = mn0; m1v = mn1;

        float s0 = 0.f, s1 = 0.f;
#pragma unroll
        for (int f = 0; f < 8; ++f) {
            sacc[f][0] = __expf(sacc[f][0] - mn0);
            sacc[f][1] = __expf(sacc[f][1] - mn0);
            sacc[f][2] = __expf(sacc[f][2] - mn1);
            sacc[f][3] = __expf(sacc[f][3] - mn1);
            s0 += sacc[f][0] + sacc[f][1];
            s1 += sacc[f][2] + sacc[f][3];
        }
        s0 += __shfl_xor_sync(0xffffffffu, s0, 1);
        s0 += __shfl_xor_sync(0xffffffffu, s0, 2);
        s1 += __shfl_xor_sync(0xffffffffu, s1, 1);
        s1 += __shfl_xor_sync(0xffffffffu, s1, 2);
        l0v = l0v * a0 + s0;
        l1v = l1v * a1 + s1;
#pragma unroll
        for (int nf = 0; nf < 16; ++nf) {
            oacc[nf][0] *= a0; oacc[nf][1] *= a0;
            oacc[nf][2] *= a1; oacc[nf][3] *= a1;
        }

        // store P as fp16 words
#pragma unroll
        for (int f = 0; f < 8; ++f) {
            Pw[(wid * 16 + lq) * FPW + f * 4 + lr]     = pack2h(sacc[f][0], sacc[f][1]);
            Pw[(wid * 16 + lq + 8) * FPW + f * 4 + lr] = pack2h(sacc[f][2], sacc[f][3]);
        }
        __syncwarp();

        // ---- O += P @ V : fp16 ----
#pragma unroll
        for (int ks = 0; ks < 4; ++ks) {
            uint32_t pa[4];
            LDM_X4(pa[0], pa[1], pa[2], pa[3],
                   sbP + (uint32_t)((wid * 16 + aRowOff) * FPW + ks * 8 + aKw) * 4);
#pragma unroll
            for (int nfp = 0; nfp < 8; ++nfp) {
                uint32_t v0a, v1a, v0b, v1b;
                LDM_X4T(v0a, v1a, v0b, v1b,
                        sbV + (uint32_t)((ks * 16 + vK) * FKS + nfp * 8 + vCol) * 4);
                uint32_t vba[2] = { v0a, v1a }, vbb[2] = { v0b, v1b };
                mma_f16(oacc[2 * nfp],     pa, vba);
                mma_f16(oacc[2 * nfp + 1], pa, vbb);
            }
        }
    }
#undef ISSUE_Q
#undef ISSUE_KV

    // epilogue: O /= l, cvt fp16, packed layout
    const float inv0 = 1.f / l0v, inv1 = 1.f / l1v;
    const int r0 = q0 + wid * 16 + lq;
#pragma unroll
    for (int nf = 0; nf < 16; ++nf) {
        const int col = h * DHEAD + nf * 8 + 2 * lr;
        *(uint32_t*)(out + ((size_t)(b * SEQ + r0)) * HDIM + col)
            = pack2h(oacc[nf][0] * inv0, oacc[nf][1] * inv0);
        *(uint32_t*)(out + ((size_t)(b * SEQ + r0 + 8)) * HDIM + col)
            = pack2h(oacc[nf][2] * inv1, oacc[nf][3] * inv1);
    }
}

// ---------------- launcher ----------------
extern "C" void kernel_launch(void* const* d_in, const int* in_sizes, int n_in,
                              void* d_out, int out_size)
{
    int iwq, ibq, iwk, ibk, iwv, ibv, iwo, iwg, iwu, iwd, iln1, iln2, icos, isin;
    if (n_in >= 2 && in_sizes[1] == SEQ * SEQ) {
        icos = 2; isin = 3; iwq = 4; ibq = 5; iwk = 6; ibk = 7; iwv = 8; ibv = 9;
        iwo = 10; iwg = 11; iwu = 12; iwd = 13; iln1 = 14; iln2 = 15;
    } else {
        iwq = 1; ibq = 2; iwk = 3; ibk = 4; iwv = 5; ibv = 6; iwo = 7; iwg = 8;
        iwu = 9; iwd = 10; iln1 = 11; iln2 = 12; icos = 14; isin = 15;
    }

    const float* hs   = (const float*)d_in[0];
    const float* wq   = (const float*)d_in[iwq];
    const float* bq   = (const float*)d_in[ibq];
    const float* wk   = (const float*)d_in[iwk];
    const float* bk   = (const float*)d_in[ibk];
    const float* wv   = (const float*)d_in[iwv];
    const float* bv   = (const float*)d_in[ibv];
    const float* wo   = (const float*)d_in[iwo];
    const float* wg   = (const float*)d_in[iwg];
    const float* wu   = (const float*)d_in[iwu];
    const float* wd   = (const float*)d_in[iwd];
    const float* ln1  = (const float*)d_in[iln1];
    const float* ln2  = (const float*)d_in[iln2];
    const float* cosT = (const float*)d_in[icos];
    const float* sinT = (const float*)d_in[isin];

    float *p_x2, *p_bqkv;
    __half *p_h1h, *p_h2h, *p_attnh, *p_qkvh, *p_gah, *p_wqkvh, *p_wh;
    cudaGetSymbolAddress((void**)&p_x2,    g_x2);
    cudaGetSymbolAddress((void**)&p_bqkv,  g_bqkv);
    cudaGetSymbolAddress((void**)&p_h1h,   g_h1h);
    cudaGetSymbolAddress((void**)&p_h2h,   g_h2h);
    cudaGetSymbolAddress((void**)&p_attnh, g_attnh);
    cudaGetSymbolAddress((void**)&p_qkvh,  g_qkvh);
    cudaGetSymbolAddress((void**)&p_gah,   g_gah);
    cudaGetSymbolAddress((void**)&p_wqkvh, g_wqkvh);
    cudaGetSymbolAddress((void**)&p_wh,    g_wh);

    // bias concat (fp32)
    cudaMemcpyAsync(p_bqkv,                bq, HDIM  * 4, cudaMemcpyDeviceToDevice, 0);
    cudaMemcpyAsync(p_bqkv + HDIM,         bk, DHEAD * 4, cudaMemcpyDeviceToDevice, 0);
    cudaMemcpyAsync(p_bqkv + HDIM + DHEAD, bv, DHEAD * 4, cudaMemcpyDeviceToDevice, 0);

    // convert weights to fp16: wq|wk|wv concat; wo; wd; wg/wu row-interleaved
    {
        int n4;
        n4 = HDIM * HDIM / 4;
        cvt_h_kernel<<<(n4 + 255) / 256, 256>>>(wq, p_wqkvh, n4);
        cvt_h_kernel<<<(n4 + 255) / 256, 256>>>(wo, p_wh + WO_OFF, n4);
        n4 = DHEAD * HDIM / 4;
        cvt_h_kernel<<<(n4 + 255) / 256, 256>>>(wk, p_wqkvh + HDIM * HDIM, n4);
        cvt_h_kernel<<<(n4 + 255) / 256, 256>>>(wv, p_wqkvh + (HDIM + DHEAD) * HDIM, n4);
        n4 = IDIM * HDIM / 4;
        cvt_h_int_kernel<<<(n4 + 255) / 256, 256>>>(wg, p_wh + WGU_OFF, 0);
        cvt_h_int_kernel<<<(n4 + 255) / 256, 256>>>(wu, p_wh + WGU_OFF, 1);
        cvt_h_kernel<<<(n4 + 255) / 256, 256>>>(wd, p_wh + WD_OFF, n4);
    }

    const int smem_gemm = 3 * (256 + 128) * GSTRIDE * 4;   // 165888 B
    cudaFuncSetAttribute(gemm_h<0>, cudaFuncAttributeMaxDynamicSharedMemorySize, smem_gemm);
    cudaFuncSetAttribute(gemm_h<1>, cudaFuncAttributeMaxDynamicSharedMemorySize, smem_gemm);
    cudaFuncSetAttribute(gemm_h<2>, cudaFuncAttributeMaxDynamicSharedMemorySize, smem_gemm);
    const int smem_flash = (128 * FKS + 4 * 64 * FKS + 128 * FPW) * 4;   // 122880 B
    cudaFuncSetAttribute(flash_mma_kernel, cudaFuncAttributeMaxDynamicSharedMemorySize, smem_flash);

    // 1) rmsnorm1 -> fp16
    rmsnorm_kernel<<<M_ROWS, 256>>>(hs, ln1, p_h1h);
    // 2) fused QKV projection -> fp16 (+bias)   [144 CTAs ~ 1 wave]
    gemm_h<0><<<dim3(QKV_N / 128, M_ROWS / 256), 256, smem_gemm>>>(
        p_h1h, p_wqkvh, p_bqkv, nullptr, p_qkvh, M_ROWS, QKV_N, HDIM);
    // 3) RoPE fp16 in-place (q pre-scaled by 1/sqrt(d))
    rope_h_kernel<<<dim3(M_ROWS, NHEADS + 1), 64>>>(p_qkvh, cosT, sinT);
    // 4) flash attention (all-fp16, cp.async K/V pipeline) -> fp16
    flash_mma_kernel<<<dim3(SEQ / 128, NHEADS, 2), 256, smem_flash>>>(p_qkvh, p_attnh);
    // 5) O projection + residual -> fp32
    gemm_h<1><<<dim3(HDIM / 128, M_ROWS / 256), 256, smem_gemm>>>(
        p_attnh, p_wh + WO_OFF, nullptr, hs, p_x2, M_ROWS, HDIM, HDIM);
    // 6) rmsnorm2 -> fp16
    rmsnorm_kernel<<<M_ROWS, 256>>>(p_x2, ln2, p_h2h);
    // 7) merged gate+up projection (interleaved weights), fused silu*up -> fp16
    gemm_h<2><<<dim3(2 * IDIM / 128, M_ROWS / 256), 256, smem_gemm>>>(
        p_h2h, p_wh + WGU_OFF, nullptr, nullptr, p_gah, M_ROWS, 2 * IDIM, HDIM);
    // 8) down projection + residual -> output (fp32)
    gemm_h<1><<<dim3(HDIM / 128, M_ROWS / 256), 256, smem_gemm>>>(
        p_gah, p_wh + WD_OFF, nullptr, p_x2, (float*)d_out, M_ROWS, HDIM, IDIM);
    (void)out_size;
}